// round 4
// baseline (speedup 1.0000x reference)
#include <cuda_runtime.h>
#include <cuda_fp16.h>

namespace {

constexpr int BB = 256;   // batch
constexpr int TT = 512;   // time steps
constexpr int DD = 64;    // feature dim
constexpr int HH = 128;   // hidden dim
constexpr int NB = 2;     // batches per block
constexpr int NT = 256;   // threads per block (8 warps)
constexpr int KC = DD + HH + DD;   // 256 combined width

// Big weight matrices live in REGISTERS (fp16 packed, per-thread K-slice).
// Shared memory holds only wgh + activations + partials: ~42 KB (static).
struct __align__(16) Smem {
    uint2 wgh[16][HH];        // 16384 : W_gh fp16, k-chunk-major
    float c[NB][192];         //  1536 : [x(64), h_pre(128)]
    float crh[NB][HH];        //  1024 : r * h_pre
    float in_s[4][NB][DD];    //  2048 : x, x_last, m, d for this step
    float h[NB][HH];          //  1024 : recurrent state
    float zg[NB][HH];         //  1024 : z gate
    float xm[NB][HH];         //  1024 : Wh_x@x + Wh_m@m
    float pZ[2][NB][HH];      //  4096 : K-half partials, z
    float pR[2][NB][HH];      //  4096 : K-half partials, r
    float pX[2][NB][HH];      //  4096 : K-half partials, xm
    float pC[2][NB][HH];      //  4096 : K-half partials, Wh_h@(r*h)
    float bgx[DD], wgxd[DD];  //   512
    float bgh_[HH], bh_[HH], bz_[HH], br_[HH];  // 2048
};
// ~43 KB < 48 KB static limit

__device__ __forceinline__ float2 mk2(float x, float y) { return make_float2(x, y); }

// Packed dual-FMA (single FFMA2 issue on sm_103a).
__device__ __forceinline__ void ffma2(float2& d, float2 a, float2 b) {
    asm("{\n\t"
        ".reg .b64 ra, rb, rd;\n\t"
        "mov.b64 ra, {%2, %3};\n\t"
        "mov.b64 rb, {%4, %5};\n\t"
        "mov.b64 rd, {%0, %1};\n\t"
        "fma.rn.f32x2 rd, ra, rb, rd;\n\t"
        "mov.b64 {%0, %1}, rd;\n\t"
        "}"
        : "+f"(d.x), "+f"(d.y)
        : "f"(a.x), "f"(a.y), "f"(b.x), "f"(b.y));
}

__device__ __forceinline__ unsigned pack_h2(float x, float y) {
    __half2 h = __floats2half2_rn(x, y);
    return *reinterpret_cast<unsigned*>(&h);
}
__device__ __forceinline__ float2 unpk(unsigned u) {
    return __half22float2(*reinterpret_cast<__half2*>(&u));
}

__global__ void __launch_bounds__(NT, 1) grud_kernel(
    const float* __restrict__ inp,   // [B,4,T,D]
    const float* __restrict__ Wgx, const float* __restrict__ bgx,
    const float* __restrict__ Wgh, const float* __restrict__ bgh,
    const float* __restrict__ Wz,  const float* __restrict__ bz,
    const float* __restrict__ Wr,  const float* __restrict__ br,
    const float* __restrict__ Wh,  const float* __restrict__ bh,
    float* __restrict__ out)         // [B,T,H]
{
    __shared__ Smem s;
    const int tid = threadIdx.x;
    const int b0  = blockIdx.x * NB;
    const int j   = tid & 127;   // output row
    const int sel = tid >> 7;    // K-half (GEMV) / batch (elementwise)

    // ---------- persistent register weights (fp16 packed) ------------------
    // wzr_r[i]: {Wz, Wr}[j][k..k+3], k = sel*128 + 4i   (i = 0..31)
    // whh_r[i]: Wh[j][64 + sel*64 + 4i ..]              (h region slice)
    // whxm_r[i]: sel=0 -> Wh[j][4i..] (x), sel=1 -> Wh[j][192+4i..] (m)
    uint4 wzr_r[32];
    uint2 whh_r[16];
    uint2 whxm_r[16];
    {
        const float* wzp = &Wz[j * KC + sel * 128];
        const float* wrp = &Wr[j * KC + sel * 128];
        #pragma unroll
        for (int i = 0; i < 32; ++i) {
            float4 a = *(const float4*)(wzp + 4 * i);
            float4 b = *(const float4*)(wrp + 4 * i);
            wzr_r[i] = make_uint4(pack_h2(a.x, a.y), pack_h2(a.z, a.w),
                                  pack_h2(b.x, b.y), pack_h2(b.z, b.w));
        }
        const float* whp = &Wh[j * KC + 64 + sel * 64];
        const float* wxp = &Wh[j * KC + (sel ? 192 : 0)];
        #pragma unroll
        for (int i = 0; i < 16; ++i) {
            float4 g = *(const float4*)(whp + 4 * i);
            whh_r[i] = make_uint2(pack_h2(g.x, g.y), pack_h2(g.z, g.w));
            float4 x = *(const float4*)(wxp + 4 * i);
            whxm_r[i] = make_uint2(pack_h2(x.x, x.y), pack_h2(x.z, x.w));
        }
    }

    // ---------- smem preamble: wgh fp16 + biases ----------------------------
    for (int lin = tid; lin < 16 * HH; lin += NT) {
        int jj = lin >> 4, q = lin & 15;
        float4 a = *(const float4*)&Wgh[jj * DD + 4 * q];
        s.wgh[q][jj] = make_uint2(pack_h2(a.x, a.y), pack_h2(a.z, a.w));
    }
    if (tid < HH) {
        s.bgh_[tid] = bgh[tid]; s.bh_[tid] = bh[tid];
        s.bz_[tid]  = bz[tid];  s.br_[tid] = br[tid];
        s.h[0][tid] = 0.f;      s.h[1][tid] = 0.f;
    }
    if (tid < DD) {
        s.bgx[tid]  = bgx[tid];
        s.wgxd[tid] = Wgx[tid * DD + tid];   // (eye * W_gx) diagonal
    }

    // ---------- input prefetch: 2 consecutive elements per thread ----------
    const int e  = tid * 2;            // 512 elements = 4ch x 2b x 64d
    const int ch = e >> 7;
    const int ib = (e >> 6) & 1;
    const int id = e & 63;
    const long ibase = ((long)((b0 + ib) * 4 + ch) * TT) * DD + id;
    float2 nx = *(const float2*)&inp[ibase];

    for (int t = 0; t < TT; ++t) {
        // publish this step's inputs, prefetch next step's
        *(float2*)&s.in_s[ch][ib][id] = nx;
        const int tn = (t + 1 < TT) ? (t + 1) : t;
        nx = *(const float2*)&inp[ibase + (long)tn * DD];
        __syncthreads();                                   // s1

        // ---- stage 0: delta_h gemv (full K=64, batch=sel) + x-update ----
        {
            float2 ag = mk2(0.f, 0.f);
            #pragma unroll
            for (int i = 0; i < 16; ++i) {
                uint2 w = s.wgh[i][j];
                float4 d4 = *(const float4*)&s.in_s[3][sel][4 * i];
                ffma2(ag, unpk(w.x), mk2(d4.x, d4.y));
                ffma2(ag, unpk(w.y), mk2(d4.z, d4.w));
            }
            float pre = ag.x + ag.y + s.bgh_[j];
            s.c[sel][DD + j] = __expf(-fmaxf(pre, 0.f)) * s.h[sel][j];
            if (j < DD) {
                float dd = s.in_s[3][sel][j];
                float dx = __expf(-fmaxf(fmaf(dd, s.wgxd[j], s.bgx[j]), 0.f));
                float m  = s.in_s[2][sel][j];
                s.c[sel][j] = m * s.in_s[0][sel][j]
                            + (1.f - m) * (dx * s.in_s[1][sel][j]);
            }
        }
        __syncthreads();                                   // s2

        // ---- stage A: z, r (+ xm) partials over K-half sel, both batches --
        {
            float2 az0 = mk2(0.f,0.f), az1 = mk2(0.f,0.f);
            float2 ar0 = mk2(0.f,0.f), ar1 = mk2(0.f,0.f);
            float2 ax0 = mk2(0.f,0.f), ax1 = mk2(0.f,0.f);
            // group 1: chunks 0..15 -> sel=0: x region; sel=1: h upper
            const float* A0 = sel ? &s.c[0][128] : &s.c[0][0];
            const float* A1 = sel ? &s.c[1][128] : &s.c[1][0];
            // group 2: chunks 16..31 -> sel=0: h lower; sel=1: m region
            const float* B0 = sel ? &s.in_s[2][0][0] : &s.c[0][64];
            const float* B1 = sel ? &s.in_s[2][1][0] : &s.c[1][64];
            #pragma unroll
            for (int i = 0; i < 16; ++i) {
                uint4 w = wzr_r[i];
                float4 c0 = *(const float4*)(A0 + 4 * i);
                float4 c1 = *(const float4*)(A1 + 4 * i);
                float2 lo0 = mk2(c0.x, c0.y), hi0 = mk2(c0.z, c0.w);
                float2 lo1 = mk2(c1.x, c1.y), hi1 = mk2(c1.z, c1.w);
                float2 wz0 = unpk(w.x), wz1 = unpk(w.y);
                float2 wr0 = unpk(w.z), wr1 = unpk(w.w);
                ffma2(az0, wz0, lo0); ffma2(az0, wz1, hi0);
                ffma2(az1, wz0, lo1); ffma2(az1, wz1, hi1);
                ffma2(ar0, wr0, lo0); ffma2(ar0, wr1, hi0);
                ffma2(ar1, wr0, lo1); ffma2(ar1, wr1, hi1);
                if (sel == 0) {   // warp-uniform: x region carries Wh_x
                    uint2 wx = whxm_r[i];
                    float2 w0 = unpk(wx.x), w1 = unpk(wx.y);
                    ffma2(ax0, w0, lo0); ffma2(ax0, w1, hi0);
                    ffma2(ax1, w0, lo1); ffma2(ax1, w1, hi1);
                }
            }
            #pragma unroll
            for (int i = 0; i < 16; ++i) {
                uint4 w = wzr_r[16 + i];
                float4 c0 = *(const float4*)(B0 + 4 * i);
                float4 c1 = *(const float4*)(B1 + 4 * i);
                float2 lo0 = mk2(c0.x, c0.y), hi0 = mk2(c0.z, c0.w);
                float2 lo1 = mk2(c1.x, c1.y), hi1 = mk2(c1.z, c1.w);
                float2 wz0 = unpk(w.x), wz1 = unpk(w.y);
                float2 wr0 = unpk(w.z), wr1 = unpk(w.w);
                ffma2(az0, wz0, lo0); ffma2(az0, wz1, hi0);
                ffma2(az1, wz0, lo1); ffma2(az1, wz1, hi1);
                ffma2(ar0, wr0, lo0); ffma2(ar0, wr1, hi0);
                ffma2(ar1, wr0, lo1); ffma2(ar1, wr1, hi1);
                if (sel == 1) {   // warp-uniform: m region carries Wh_m
                    uint2 wx = whxm_r[i];
                    float2 w0 = unpk(wx.x), w1 = unpk(wx.y);
                    ffma2(ax0, w0, lo0); ffma2(ax0, w1, hi0);
                    ffma2(ax1, w0, lo1); ffma2(ax1, w1, hi1);
                }
            }
            s.pZ[sel][0][j] = az0.x + az0.y;
            s.pZ[sel][1][j] = az1.x + az1.y;
            s.pR[sel][0][j] = ar0.x + ar0.y;
            s.pR[sel][1][j] = ar1.x + ar1.y;
            s.pX[sel][0][j] = ax0.x + ax0.y;
            s.pX[sel][1][j] = ax1.x + ax1.y;
        }
        __syncthreads();                                   // s3

        // ---- A-reduce: gates, r*h_pre, xm sum (batch = sel) ----
        {
            float zp = s.pZ[0][sel][j] + s.pZ[1][sel][j] + s.bz_[j];
            float rp = s.pR[0][sel][j] + s.pR[1][sel][j] + s.br_[j];
            float z  = __fdividef(1.f, 1.f + __expf(-zp));
            float r  = __fdividef(1.f, 1.f + __expf(-rp));
            s.zg[sel][j]  = z;
            s.crh[sel][j] = r * s.c[sel][DD + j];
            s.xm[sel][j]  = s.pX[0][sel][j] + s.pX[1][sel][j];
        }
        __syncthreads();                                   // s4

        // ---- stage C: Wh_h @ (r*h_pre), K-half sel, both batches ----
        {
            const float* R0 = &s.crh[0][sel * 64];
            const float* R1 = &s.crh[1][sel * 64];
            float2 a0 = mk2(0.f,0.f), a1 = mk2(0.f,0.f);
            #pragma unroll
            for (int i = 0; i < 16; ++i) {
                uint2 w = whh_r[i];
                float4 r0 = *(const float4*)(R0 + 4 * i);
                float4 r1 = *(const float4*)(R1 + 4 * i);
                float2 w0 = unpk(w.x), w1 = unpk(w.y);
                ffma2(a0, w0, mk2(r0.x, r0.y)); ffma2(a0, w1, mk2(r0.z, r0.w));
                ffma2(a1, w0, mk2(r1.x, r1.y)); ffma2(a1, w1, mk2(r1.z, r1.w));
            }
            s.pC[sel][0][j] = a0.x + a0.y;
            s.pC[sel][1][j] = a1.x + a1.y;
        }
        __syncthreads();                                   // s5

        // ---- final: tanh, blend, state update, store (batch = sel) ----
        {
            float pre = s.pC[0][sel][j] + s.pC[1][sel][j]
                      + s.xm[sel][j] + s.bh_[j];
            float e2  = __expf(2.f * pre);
            float ht  = 1.f - __fdividef(2.f, e2 + 1.f);   // tanh
            float z   = s.zg[sel][j];
            float hp  = s.c[sel][DD + j];
            float hn  = fmaf(z, ht - hp, hp);
            s.h[sel][j] = hn;
            out[((long)(b0 + sel) * TT + t) * HH + j] = hn;
        }
        // no trailing barrier: next-step in_s publish races nothing (all
        // in_s readers finished before s3), and s1 orders h/c/out updates.
    }
}

} // namespace

extern "C" void kernel_launch(void* const* d_in, const int* in_sizes, int n_in,
                              void* d_out, int out_size) {
    const float* inp = (const float*)d_in[0];
    const float* Wgx = (const float*)d_in[1];
    const float* bgx = (const float*)d_in[2];
    const float* Wgh = (const float*)d_in[3];
    const float* bgh = (const float*)d_in[4];
    const float* Wz  = (const float*)d_in[5];
    const float* bz  = (const float*)d_in[6];
    const float* Wr  = (const float*)d_in[7];
    const float* br  = (const float*)d_in[8];
    const float* Wh  = (const float*)d_in[9];
    const float* bh  = (const float*)d_in[10];
    float* out = (float*)d_out;

    grud_kernel<<<BB / NB, NT>>>(
        inp, Wgx, bgx, Wgh, bgh, Wz, bz, Wr, br, Wh, bh, out);
}

// round 5
// speedup vs baseline: 3.2652x; 3.2652x over previous
#include <cuda_runtime.h>
#include <cuda_fp16.h>

namespace {

constexpr int BB = 256, TT = 512, DD = 64, HH = 128, KC = 256;

// Precomputed per (b,t): q=0 zpre, q=1 rpre, q=2 xmpre(+bh), q=3 delta_h
// Layout [b][t][q][j]  -> 256*512*4*128 floats = 256 MB
__device__ float g_pre[(size_t)BB * TT * 4 * HH];

__device__ __forceinline__ float2 mk2(float x, float y) { return make_float2(x, y); }

// Packed dual-FMA (single FFMA2 issue on sm_103a).
__device__ __forceinline__ void ffma2(float2& d, float2 a, float2 b) {
    asm("{\n\t"
        ".reg .b64 ra, rb, rd;\n\t"
        "mov.b64 ra, {%2, %3};\n\t"
        "mov.b64 rb, {%4, %5};\n\t"
        "mov.b64 rd, {%0, %1};\n\t"
        "fma.rn.f32x2 rd, ra, rb, rd;\n\t"
        "mov.b64 {%0, %1}, rd;\n\t"
        "}"
        : "+f"(d.x), "+f"(d.y)
        : "f"(a.x), "f"(a.y), "f"(b.x), "f"(b.y));
}

__device__ __forceinline__ unsigned pack_h2(float x, float y) {
    __half2 h = __floats2half2_rn(x, y);
    return *reinterpret_cast<unsigned*>(&h);
}
__device__ __forceinline__ float2 unpk(unsigned u) {
    return __half22float2(*reinterpret_cast<__half2*>(&u));
}

// ===========================================================================
// Kernel 1: time-parallel precompute.  grid=128 (b-pair), NT=512.
// thread = (q4 = tid>>7, j = tid&127); q4 selects quantity {z, r, xm, dh}.
// Each thread holds its weight row in fp16 registers; activations staged in
// smem (ping-pong, 1 barrier/iter); 4 rows (2 b x 2 t) per iteration.
// ===========================================================================
__global__ void __launch_bounds__(512, 1) pre_kernel(
    const float* __restrict__ inp,
    const float* __restrict__ Wgx, const float* __restrict__ bgx,
    const float* __restrict__ Wgh, const float* __restrict__ bgh,
    const float* __restrict__ Wz,  const float* __restrict__ bz,
    const float* __restrict__ Wr,  const float* __restrict__ br,
    const float* __restrict__ Wh,  const float* __restrict__ bh)
{
    __shared__ float axm[2][2][2][128];   // [buf][b][tt][ x(64) | m(64) ]
    __shared__ float ad [2][2][2][64];    // [buf][b][tt][ d ]

    const int tid = threadIdx.x;
    const int b0  = blockIdx.x * 2;
    const int q4  = tid >> 7;
    const int j   = tid & 127;

    // ---- per-thread weight row (fp16 packed) ----
    unsigned wgt[64];
    #pragma unroll
    for (int i = 0; i < 64; ++i) wgt[i] = 0;
    float bias;
    if (q4 <= 1) {
        const float* W = (q4 == 0) ? Wz : Wr;
        #pragma unroll
        for (int i = 0; i < 32; ++i) {
            float2 a = *(const float2*)&W[j * KC + 2 * i];          // x cols
            wgt[i] = pack_h2(a.x, a.y);
            float2 b = *(const float2*)&W[j * KC + 192 + 2 * i];    // m cols
            wgt[32 + i] = pack_h2(b.x, b.y);
        }
        bias = (q4 == 0) ? bz[j] : br[j];
    } else if (q4 == 2) {
        #pragma unroll
        for (int i = 0; i < 32; ++i) {
            float2 a = *(const float2*)&Wh[j * KC + 2 * i];
            wgt[i] = pack_h2(a.x, a.y);
            float2 b = *(const float2*)&Wh[j * KC + 192 + 2 * i];
            wgt[32 + i] = pack_h2(b.x, b.y);
        }
        bias = bh[j];
    } else {
        #pragma unroll
        for (int i = 0; i < 32; ++i) {
            float2 a = *(const float2*)&Wgh[j * DD + 2 * i];
            wgt[i] = pack_h2(a.x, a.y);
        }
        bias = bgh[j];
    }

    // ---- loader state (threads 0..255): one (b, tt, dim) slot each ----
    const int lb  = (tid >> 7) & 1;
    const int ltt = (tid >> 6) & 1;
    const int ld  = tid & 63;
    float wgxd = 0.f, bgxv = 0.f;
    long lbase = 0;
    if (tid < 256) {
        wgxd  = Wgx[ld * DD + ld];
        bgxv  = bgx[ld];
        lbase = ((long)(b0 + lb) * 4) * TT * DD + ld;   // + ch*TT*DD + t*DD
    }
    const long CH = (long)TT * DD;
    float rx = 0.f, rxl = 0.f, rm = 0.f, rd_ = 0.f;
    if (tid < 256) {
        long o = lbase + (long)ltt * DD;                // t = 0 + ltt
        rx  = inp[o];
        rxl = inp[o + CH];
        rm  = inp[o + 2 * CH];
        rd_ = inp[o + 3 * CH];
    }

    for (int it = 0; it < TT / 2; ++it) {
        const int buf = it & 1;
        if (tid < 256) {
            float dx = __expf(-fmaxf(fmaf(rd_, wgxd, bgxv), 0.f));
            float xt = rm * rx + (1.f - rm) * (dx * rxl);
            axm[buf][lb][ltt][ld]      = xt;
            axm[buf][lb][ltt][64 + ld] = rm;
            ad [buf][lb][ltt][ld]      = rd_;
            int tnext = 2 * (it + 1) + ltt;
            if (tnext > TT - 1) tnext = TT - 1;
            long o = lbase + (long)tnext * DD;
            rx  = inp[o];
            rxl = inp[o + CH];
            rm  = inp[o + 2 * CH];
            rd_ = inp[o + 3 * CH];
        }
        __syncthreads();

        float2 acc[4];
        #pragma unroll
        for (int r = 0; r < 4; ++r) acc[r] = mk2(0.f, 0.f);

        if (q4 < 3) {
            #pragma unroll
            for (int i = 0; i < 32; ++i) {
                float2 w0 = unpk(wgt[2 * i]);
                float2 w1 = unpk(wgt[2 * i + 1]);
                #pragma unroll
                for (int r = 0; r < 4; ++r) {
                    float4 a = *(const float4*)&axm[buf][r >> 1][r & 1][4 * i];
                    ffma2(acc[r], w0, mk2(a.x, a.y));
                    ffma2(acc[r], w1, mk2(a.z, a.w));
                }
            }
        } else {
            #pragma unroll
            for (int i = 0; i < 16; ++i) {
                float2 w0 = unpk(wgt[2 * i]);
                float2 w1 = unpk(wgt[2 * i + 1]);
                #pragma unroll
                for (int r = 0; r < 4; ++r) {
                    float4 a = *(const float4*)&ad[buf][r >> 1][r & 1][4 * i];
                    ffma2(acc[r], w0, mk2(a.x, a.y));
                    ffma2(acc[r], w1, mk2(a.z, a.w));
                }
            }
        }

        #pragma unroll
        for (int r = 0; r < 4; ++r) {
            float v = acc[r].x + acc[r].y + bias;
            if (q4 == 3) v = __expf(-fmaxf(v, 0.f));
            int b = b0 + (r >> 1);
            int t = 2 * it + (r & 1);
            g_pre[(((size_t)b * TT + t) * 4 + q4) * HH + j] = v;
        }
        // no second barrier: ping-pong buffers + the single barrier per iter
        // order buffer reuse safely.
    }
}

// ===========================================================================
// Kernel 2: sequential scan.  grid=128 (b-pair), NT=256.
// thread = (g = tid>>7, j = tid&127). g = K-half in GEMV stages, batch in
// elementwise stages.  In-loop weights (Wz_h, Wr_h, Wh_h rows) live in
// registers: 96 u32 persistent -- safely under budget.
// ===========================================================================
__global__ void __launch_bounds__(256, 1) scan_kernel(
    const float* __restrict__ Wz, const float* __restrict__ Wr,
    const float* __restrict__ Wh,
    float* __restrict__ out)         // [B,T,H]
{
    __shared__ float hpre[2][HH];
    __shared__ float crh [2][HH];
    __shared__ float pZ[2][2][HH];   // [kh][b][j]
    __shared__ float pR[2][2][HH];
    __shared__ float pC[2][2][HH];

    const int tid = threadIdx.x;
    const int b0  = blockIdx.x * 2;
    const int g   = tid >> 7;
    const int j   = tid & 127;

    // weight rows over the h-region of combined (cols 64..191), K-half g
    unsigned wz_[32], wr_[32], wh_[32];
    {
        const int koff = 64 + g * 64;
        #pragma unroll
        for (int i = 0; i < 32; ++i) {
            float2 a = *(const float2*)&Wz[j * KC + koff + 2 * i];
            wz_[i] = pack_h2(a.x, a.y);
            float2 b = *(const float2*)&Wr[j * KC + koff + 2 * i];
            wr_[i] = pack_h2(b.x, b.y);
            float2 c = *(const float2*)&Wh[j * KC + koff + 2 * i];
            wh_[i] = pack_h2(c.x, c.y);
        }
    }
    hpre[g][j] = 0.f;

    // per-thread scratch stream: 4 scalars per step at [b0+g][t][q][j]
    const float* prb = &g_pre[((size_t)(b0 + g) * TT) * 4 * HH + j];
    float4 pf_c, pf_n, pf_nn;
    {
        pf_c = make_float4(prb[0], prb[HH], prb[2 * HH], prb[3 * HH]);
        size_t o = (size_t)4 * HH;
        pf_n = make_float4(prb[o], prb[o + HH], prb[o + 2 * HH], prb[o + 3 * HH]);
    }
    __syncthreads();

    float zreg = 0.f, hp_own = 0.f;

    for (int t = 0; t < TT; ++t) {
        // ---- stage A: z, r partials over h_pre (K-half g, both batches) ----
        {
            float2 az0 = mk2(0.f,0.f), az1 = mk2(0.f,0.f);
            float2 ar0 = mk2(0.f,0.f), ar1 = mk2(0.f,0.f);
            #pragma unroll
            for (int i = 0; i < 16; ++i) {
                float2 w0 = unpk(wz_[2 * i]);
                float2 w1 = unpk(wz_[2 * i + 1]);
                float2 v0 = unpk(wr_[2 * i]);
                float2 v1 = unpk(wr_[2 * i + 1]);
                float4 h0 = *(const float4*)&hpre[0][g * 64 + 4 * i];
                float4 h1 = *(const float4*)&hpre[1][g * 64 + 4 * i];
                float2 lo0 = mk2(h0.x, h0.y), hi0 = mk2(h0.z, h0.w);
                float2 lo1 = mk2(h1.x, h1.y), hi1 = mk2(h1.z, h1.w);
                ffma2(az0, w0, lo0); ffma2(az0, w1, hi0);
                ffma2(az1, w0, lo1); ffma2(az1, w1, hi1);
                ffma2(ar0, v0, lo0); ffma2(ar0, v1, hi0);
                ffma2(ar1, v0, lo1); ffma2(ar1, v1, hi1);
            }
            pZ[g][0][j] = az0.x + az0.y;
            pZ[g][1][j] = az1.x + az1.y;
            pR[g][0][j] = ar0.x + ar0.y;
            pR[g][1][j] = ar1.x + ar1.y;
        }
        // prefetch scratch for t+2
        {
            int t2 = (t + 2 < TT) ? t + 2 : TT - 1;
            size_t o = (size_t)t2 * 4 * HH;
            pf_nn = make_float4(prb[o], prb[o + HH],
                                prb[o + 2 * HH], prb[o + 3 * HH]);
        }
        __syncthreads();                                   // bar 1

        // ---- reduce: gates + r*h_pre (role: batch = g) ----
        {
            float zp = pZ[0][g][j] + pZ[1][g][j] + pf_c.x;
            float rp = pR[0][g][j] + pR[1][g][j] + pf_c.y;
            zreg = __fdividef(1.f, 1.f + __expf(-zp));
            float r = __fdividef(1.f, 1.f + __expf(-rp));
            hp_own = hpre[g][j];
            crh[g][j] = r * hp_own;
        }
        __syncthreads();                                   // bar 2

        // ---- stage C: Wh_h @ (r*h_pre) (K-half g, both batches) ----
        {
            float2 a0 = mk2(0.f,0.f), a1 = mk2(0.f,0.f);
            #pragma unroll
            for (int i = 0; i < 16; ++i) {
                float2 w0 = unpk(wh_[2 * i]);
                float2 w1 = unpk(wh_[2 * i + 1]);
                float4 c0 = *(const float4*)&crh[0][g * 64 + 4 * i];
                float4 c1 = *(const float4*)&crh[1][g * 64 + 4 * i];
                ffma2(a0, w0, mk2(c0.x, c0.y)); ffma2(a0, w1, mk2(c0.z, c0.w));
                ffma2(a1, w0, mk2(c1.x, c1.y)); ffma2(a1, w1, mk2(c1.z, c1.w));
            }
            pC[g][0][j] = a0.x + a0.y;
            pC[g][1][j] = a1.x + a1.y;
        }
        __syncthreads();                                   // bar 3

        // ---- final: tanh, blend, state + output (role: batch = g) ----
        {
            float pre = pC[0][g][j] + pC[1][g][j] + pf_c.z;  // bh inside xmpre
            float e2  = __expf(2.f * pre);
            float ht  = 1.f - __fdividef(2.f, e2 + 1.f);     // tanh
            float hn  = fmaf(zreg, ht - hp_own, hp_own);
            out[((size_t)(b0 + g) * TT + t) * HH + j] = hn;
            hpre[g][j] = pf_n.w * hn;                        // dh(t+1) * h_t
            pf_c = pf_n;
            pf_n = pf_nn;
        }
        __syncthreads();                                   // bar 4
    }
}

} // namespace

extern "C" void kernel_launch(void* const* d_in, const int* in_sizes, int n_in,
                              void* d_out, int out_size) {
    const float* inp = (const float*)d_in[0];
    const float* Wgx = (const float*)d_in[1];
    const float* bgx = (const float*)d_in[2];
    const float* Wgh = (const float*)d_in[3];
    const float* bgh = (const float*)d_in[4];
    const float* Wz  = (const float*)d_in[5];
    const float* bz  = (const float*)d_in[6];
    const float* Wr  = (const float*)d_in[7];
    const float* br  = (const float*)d_in[8];
    const float* Wh  = (const float*)d_in[9];
    const float* bh  = (const float*)d_in[10];
    float* out = (float*)d_out;

    pre_kernel<<<BB / 2, 512>>>(inp, Wgx, bgx, Wgh, bgh,
                                Wz, bz, Wr, br, Wh, bh);
    scan_kernel<<<BB / 2, 256>>>(Wz, Wr, Wh, out);
}